// round 1
// baseline (speedup 1.0000x reference)
#include <cuda_runtime.h>
#include <cstdint>

#define NN 50000
#define EE 800000
#define DD 96
#define FF 128

// ---------------- scratch (static device globals; no allocs) ----------------
__device__ __align__(16) float g_hA[NN * DD];
__device__ __align__(16) float g_hB[NN * DD];
__device__ __align__(16) float g_agg0[NN * DD];
__device__ __align__(16) float g_agg1[NN * DD];
__device__ __align__(16) float g_WfT[FF * DD];
__device__ int g_deg0[NN];
__device__ int g_deg1[NN];
__device__ int g_rowptr[NN + 1];
__device__ int g_cur[NN];
__device__ int g_col[EE];

// ---------------- CSR build ----------------
__global__ void k_hist(const int* __restrict__ ei, const float* __restrict__ attr,
                       int* __restrict__ deg0, int* __restrict__ deg1, int E) {
    int e = blockIdx.x * blockDim.x + threadIdx.x;
    if (e >= E) return;
    int dst = ei[E + e];
    float a0 = attr[2 * e], a1 = attr[2 * e + 1];
    if (a1 > a0) atomicAdd(&deg1[dst], 1);
    else         atomicAdd(&deg0[dst], 1);
}

__global__ void k_scan(const int* __restrict__ deg0, const int* __restrict__ deg1,
                       int* __restrict__ rowptr, int N) {
    __shared__ int part[1024];
    int tid = threadIdx.x;
    const int CH = (N + 1023) / 1024;
    int start = tid * CH;
    int end = start + CH; if (end > N) end = N; if (start > N) start = N;
    int s = 0;
    for (int i = start; i < end; i++) s += deg0[i] + deg1[i];
    part[tid] = s;
    __syncthreads();
    // Hillis-Steele inclusive scan
    for (int off = 1; off < 1024; off <<= 1) {
        int v = (tid >= off) ? part[tid - off] : 0;
        __syncthreads();
        part[tid] += v;
        __syncthreads();
    }
    int excl = (tid == 0) ? 0 : part[tid - 1];
    for (int i = start; i < end; i++) { rowptr[i] = excl; excl += deg0[i] + deg1[i]; }
    if (tid == 1023) rowptr[N] = part[1023];
}

__global__ void k_fill(const int* __restrict__ ei, const float* __restrict__ attr,
                       const int* __restrict__ rowptr, int* __restrict__ cur,
                       int* __restrict__ col, int E) {
    int e = blockIdx.x * blockDim.x + threadIdx.x;
    if (e >= E) return;
    int src = ei[e];
    int dst = ei[E + e];
    float a0 = attr[2 * e], a1 = attr[2 * e + 1];
    int r = (a1 > a0) ? 1 : 0;
    int pos = rowptr[dst] + atomicAdd(&cur[dst], 1);
    col[pos] = src | (r << 30);
}

__global__ void k_twf(const float* __restrict__ Wf, float* __restrict__ WfT) {
    int i = blockIdx.x * blockDim.x + threadIdx.x; // over 96*128
    if (i < DD * FF) {
        int d = i / FF, k = i % FF;
        WfT[k * DD + d] = Wf[i];
    }
}

// ---------------- aggregation (gather-based, warp per node) ----------------
__global__ void k_agg(const float* __restrict__ h, const int* __restrict__ rowptr,
                      const int* __restrict__ col, const int* __restrict__ deg0,
                      const int* __restrict__ deg1, float* __restrict__ a0g,
                      float* __restrict__ a1g, int N) {
    int warp = (blockIdx.x * blockDim.x + threadIdx.x) >> 5;
    int lane = threadIdx.x & 31;
    if (warp >= N) return;
    int n = warp;
    int e0 = rowptr[n], e1 = rowptr[n + 1];
    float x0 = 0.f, x1 = 0.f, x2 = 0.f;   // relation 0
    float y0 = 0.f, y1 = 0.f, y2 = 0.f;   // relation 1
    int e = e0;
    for (; e + 1 < e1; e += 2) {
        int pa = __ldg(&col[e]);
        int pb = __ldg(&col[e + 1]);
        const float* ha = h + (size_t)(pa & 0x3FFFFFFF) * DD;
        const float* hb = h + (size_t)(pb & 0x3FFFFFFF) * DD;
        float a0v = __ldg(ha + lane), a1v = __ldg(ha + lane + 32), a2v = __ldg(ha + lane + 64);
        float b0v = __ldg(hb + lane), b1v = __ldg(hb + lane + 32), b2v = __ldg(hb + lane + 64);
        if (pa & (1 << 30)) { y0 += a0v; y1 += a1v; y2 += a2v; }
        else                { x0 += a0v; x1 += a1v; x2 += a2v; }
        if (pb & (1 << 30)) { y0 += b0v; y1 += b1v; y2 += b2v; }
        else                { x0 += b0v; x1 += b1v; x2 += b2v; }
    }
    if (e < e1) {
        int p = __ldg(&col[e]);
        const float* hr = h + (size_t)(p & 0x3FFFFFFF) * DD;
        float v0 = __ldg(hr + lane), v1 = __ldg(hr + lane + 32), v2 = __ldg(hr + lane + 64);
        if (p & (1 << 30)) { y0 += v0; y1 += v1; y2 += v2; }
        else               { x0 += v0; x1 += v1; x2 += v2; }
    }
    float i0 = 1.f / fmaxf((float)__ldg(&deg0[n]), 1.f);
    float i1 = 1.f / fmaxf((float)__ldg(&deg1[n]), 1.f);
    float* o0 = a0g + (size_t)n * DD;
    float* o1 = a1g + (size_t)n * DD;
    o0[lane] = x0 * i0; o0[lane + 32] = x1 * i0; o0[lane + 64] = x2 * i0;
    o1[lane] = y0 * i1; o1[lane + 32] = y1 * i1; o1[lane + 64] = y2 * i1;
}

// rank-4 outer-product FMA: A[dd] += sum_kk V[kk] * Rkk[dd]
#define MM4(A, V, R0, R1, R2, R3) do {                                          \
    A.x = fmaf(V.x, R0.x, A.x); A.x = fmaf(V.y, R1.x, A.x);                     \
    A.x = fmaf(V.z, R2.x, A.x); A.x = fmaf(V.w, R3.x, A.x);                     \
    A.y = fmaf(V.x, R0.y, A.y); A.y = fmaf(V.y, R1.y, A.y);                     \
    A.y = fmaf(V.z, R2.y, A.y); A.y = fmaf(V.w, R3.y, A.y);                     \
    A.z = fmaf(V.x, R0.z, A.z); A.z = fmaf(V.y, R1.z, A.z);                     \
    A.z = fmaf(V.z, R2.z, A.z); A.z = fmaf(V.w, R3.z, A.z);                     \
    A.w = fmaf(V.x, R0.w, A.w); A.w = fmaf(V.y, R1.w, A.w);                     \
    A.w = fmaf(V.z, R2.w, A.w); A.w = fmaf(V.w, R3.w, A.w);                     \
} while (0)

// ---------------- initial linear: h = relu(x @ WfT + bf) ----------------
// block: 192 threads = 24 d-quads x 8 node-groups; 32 nodes/block
__global__ __launch_bounds__(192) void k_lin(const float* __restrict__ x,
                                             const float* __restrict__ WfT,
                                             const float* __restrict__ bf,
                                             float* __restrict__ out, int N) {
    __shared__ float xs[32 * FF];
    int tid = threadIdx.x;
    int nb = blockIdx.x * 32;
    int base4 = nb * (FF / 4);
    int tot4 = N * (FF / 4);
    const float4 z4 = make_float4(0.f, 0.f, 0.f, 0.f);
    for (int i = tid; i < 32 * FF / 4; i += 192) {
        float4 v = (base4 + i < tot4) ? __ldg((const float4*)x + base4 + i) : z4;
        ((float4*)xs)[i] = v;
    }
    __syncthreads();
    int dq = tid % 24;
    int jb = (tid / 24) * 4;
    float4 b4 = __ldg((const float4*)bf + dq);
    float4 acc[4];
#pragma unroll
    for (int j = 0; j < 4; j++) acc[j] = b4;
    const float4* W4 = (const float4*)WfT;
#pragma unroll 4
    for (int k = 0; k < FF; k += 4) {
        float4 w0 = __ldg(W4 + (k + 0) * 24 + dq);
        float4 w1 = __ldg(W4 + (k + 1) * 24 + dq);
        float4 w2 = __ldg(W4 + (k + 2) * 24 + dq);
        float4 w3 = __ldg(W4 + (k + 3) * 24 + dq);
#pragma unroll
        for (int j = 0; j < 4; j++) {
            float4 v = *(const float4*)&xs[(jb + j) * FF + k];
            MM4(acc[j], v, w0, w1, w2, w3);
        }
    }
#pragma unroll
    for (int j = 0; j < 4; j++) {
        int n = nb + jb + j;
        if (n < N) {
            float4 a = acc[j];
            a.x = fmaxf(a.x, 0.f); a.y = fmaxf(a.y, 0.f);
            a.z = fmaxf(a.z, 0.f); a.w = fmaxf(a.w, 0.f);
            ((float4*)(out + (size_t)n * DD))[dq] = a;
        }
    }
}

// ---------------- combine: out = relu(h@root + bias + a0@W0 + a1@W1) ----------------
__global__ __launch_bounds__(192) void k_combine(const float* __restrict__ h,
                                                 const float* __restrict__ a0g,
                                                 const float* __restrict__ a1g,
                                                 const float* __restrict__ root,
                                                 const float* __restrict__ W0,
                                                 const float* __restrict__ W1,
                                                 const float* __restrict__ bias,
                                                 float* __restrict__ out, int N) {
    __shared__ float hs[32 * DD];
    __shared__ float s0[32 * DD];
    __shared__ float s1[32 * DD];
    int tid = threadIdx.x;
    int nb = blockIdx.x * 32;
    int base4 = nb * (DD / 4);
    int tot4 = N * (DD / 4);
    const float4 z4 = make_float4(0.f, 0.f, 0.f, 0.f);
    for (int i = tid; i < 32 * DD / 4; i += 192) {
        bool ok = (base4 + i < tot4);
        ((float4*)hs)[i] = ok ? __ldg((const float4*)h + base4 + i) : z4;
        ((float4*)s0)[i] = ok ? __ldg((const float4*)a0g + base4 + i) : z4;
        ((float4*)s1)[i] = ok ? __ldg((const float4*)a1g + base4 + i) : z4;
    }
    __syncthreads();
    int dq = tid % 24;
    int jb = (tid / 24) * 4;
    float4 b4 = __ldg((const float4*)bias + dq);
    float4 acc[4];
#pragma unroll
    for (int j = 0; j < 4; j++) acc[j] = b4;
    const float4* R4 = (const float4*)root;
    const float4* U4 = (const float4*)W0;
    const float4* V4 = (const float4*)W1;
#pragma unroll 2
    for (int k = 0; k < DD; k += 4) {
        float4 r0 = __ldg(R4 + (k + 0) * 24 + dq);
        float4 r1 = __ldg(R4 + (k + 1) * 24 + dq);
        float4 r2 = __ldg(R4 + (k + 2) * 24 + dq);
        float4 r3 = __ldg(R4 + (k + 3) * 24 + dq);
        float4 u0 = __ldg(U4 + (k + 0) * 24 + dq);
        float4 u1 = __ldg(U4 + (k + 1) * 24 + dq);
        float4 u2 = __ldg(U4 + (k + 2) * 24 + dq);
        float4 u3 = __ldg(U4 + (k + 3) * 24 + dq);
        float4 v0 = __ldg(V4 + (k + 0) * 24 + dq);
        float4 v1 = __ldg(V4 + (k + 1) * 24 + dq);
        float4 v2 = __ldg(V4 + (k + 2) * 24 + dq);
        float4 v3 = __ldg(V4 + (k + 3) * 24 + dq);
#pragma unroll
        for (int j = 0; j < 4; j++) {
            float4 hv = *(const float4*)&hs[(jb + j) * DD + k];
            float4 p0 = *(const float4*)&s0[(jb + j) * DD + k];
            float4 p1 = *(const float4*)&s1[(jb + j) * DD + k];
            MM4(acc[j], hv, r0, r1, r2, r3);
            MM4(acc[j], p0, u0, u1, u2, u3);
            MM4(acc[j], p1, v0, v1, v2, v3);
        }
    }
#pragma unroll
    for (int j = 0; j < 4; j++) {
        int n = nb + jb + j;
        if (n < N) {
            float4 a = acc[j];
            a.x = fmaxf(a.x, 0.f); a.y = fmaxf(a.y, 0.f);
            a.z = fmaxf(a.z, 0.f); a.w = fmaxf(a.w, 0.f);
            ((float4*)(out + (size_t)n * DD))[dq] = a;
        }
    }
}

// ---------------- launch ----------------
extern "C" void kernel_launch(void* const* d_in, const int* in_sizes, int n_in,
                              void* d_out, int out_size) {
    const float* x    = (const float*)d_in[0];
    const int*   ei   = (const int*)d_in[1];
    const float* attr = (const float*)d_in[2];
    const float* Wf   = (const float*)d_in[3];
    const float* bf   = (const float*)d_in[4];
    const float* W    = (const float*)d_in[5];
    const float* root = (const float*)d_in[6];
    const float* bias = (const float*)d_in[7];
    float* out = (float*)d_out;

    int E = in_sizes[1] / 2;
    int N = in_sizes[0] / FF;

    void *pA, *pB, *p0, *p1, *pT, *pd0, *pd1, *prp, *pc, *pcol;
    cudaGetSymbolAddress(&pA, g_hA);
    cudaGetSymbolAddress(&pB, g_hB);
    cudaGetSymbolAddress(&p0, g_agg0);
    cudaGetSymbolAddress(&p1, g_agg1);
    cudaGetSymbolAddress(&pT, g_WfT);
    cudaGetSymbolAddress(&pd0, g_deg0);
    cudaGetSymbolAddress(&pd1, g_deg1);
    cudaGetSymbolAddress(&prp, g_rowptr);
    cudaGetSymbolAddress(&pc, g_cur);
    cudaGetSymbolAddress(&pcol, g_col);

    cudaMemsetAsync(pd0, 0, N * sizeof(int), 0);
    cudaMemsetAsync(pd1, 0, N * sizeof(int), 0);
    cudaMemsetAsync(pc, 0, N * sizeof(int), 0);

    k_hist<<<(E + 255) / 256, 256>>>(ei, attr, (int*)pd0, (int*)pd1, E);
    k_scan<<<1, 1024>>>((int*)pd0, (int*)pd1, (int*)prp, N);
    k_fill<<<(E + 255) / 256, 256>>>(ei, attr, (int*)prp, (int*)pc, (int*)pcol, E);
    k_twf<<<(DD * FF + 255) / 256, 256>>>(Wf, (float*)pT);
    k_lin<<<(N + 31) / 32, 192>>>(x, (const float*)pT, bf, (float*)pA, N);

    const float* W0 = W;
    const float* W1 = W + DD * DD;
    float* hin = (float*)pA;
    float* hout = (float*)pB;
    for (int it = 0; it < 3; it++) {
        k_agg<<<(N * 32 + 255) / 256, 256>>>(hin, (int*)prp, (int*)pcol,
                                             (int*)pd0, (int*)pd1,
                                             (float*)p0, (float*)p1, N);
        float* o = (it == 2) ? out : hout;
        k_combine<<<(N + 31) / 32, 192>>>(hin, (float*)p0, (float*)p1,
                                          root, W0, W1, bias, o, N);
        float* t = hin; hin = hout; hout = t;
    }
}

// round 2
// speedup vs baseline: 1.5347x; 1.5347x over previous
#include <cuda_runtime.h>
#include <cstdint>

#define NN 50000
#define EE 800000
#define DD 96
#define FF 128

// ---------------- scratch (static device globals; no allocs) ----------------
__device__ __align__(16) float g_hA[NN * DD];
__device__ __align__(16) float g_hB[NN * DD];
__device__ __align__(16) float g_T[NN * 3 * DD];   // [N][288]: root | rel0 | rel1
__device__ __align__(16) float g_WfT[FF * DD];
__device__ int g_deg0[NN];
__device__ int g_deg1[NN];
__device__ int g_rowptr[NN + 1];
__device__ int g_cur[NN];
__device__ int g_col[EE];

// ---------------- prep: zero counters + transpose Wf ----------------
__global__ void k_prep(const float* __restrict__ Wf, float* __restrict__ WfT,
                       int* __restrict__ deg0, int* __restrict__ deg1,
                       int* __restrict__ cur, int N) {
    int i = blockIdx.x * blockDim.x + threadIdx.x;
    if (i < N) { deg0[i] = 0; deg1[i] = 0; cur[i] = 0; }
    if (i < DD * FF) {           // Wf is [d][k] row-major -> WfT [k][d]
        int d = i >> 7, k = i & 127;
        WfT[k * DD + d] = Wf[i];
    }
}

// ---------------- CSR build ----------------
__global__ void k_hist(const int* __restrict__ ei, const float* __restrict__ attr,
                       int* __restrict__ deg0, int* __restrict__ deg1, int E) {
    int e = blockIdx.x * blockDim.x + threadIdx.x;
    if (e >= E) return;
    int dst = ei[E + e];
    float a0 = attr[2 * e], a1 = attr[2 * e + 1];
    if (a1 > a0) atomicAdd(&deg1[dst], 1);
    else         atomicAdd(&deg0[dst], 1);
}

__global__ void k_scan(const int* __restrict__ deg0, const int* __restrict__ deg1,
                       int* __restrict__ rowptr, int N) {
    __shared__ int part[1024];
    int tid = threadIdx.x;
    const int CH = (N + 1023) / 1024;
    int start = tid * CH;
    int end = start + CH; if (end > N) end = N; if (start > N) start = N;
    int s = 0;
    for (int i = start; i < end; i++) s += deg0[i] + deg1[i];
    part[tid] = s;
    __syncthreads();
    for (int off = 1; off < 1024; off <<= 1) {
        int v = (tid >= off) ? part[tid - off] : 0;
        __syncthreads();
        part[tid] += v;
        __syncthreads();
    }
    int excl = (tid == 0) ? 0 : part[tid - 1];
    for (int i = start; i < end; i++) { rowptr[i] = excl; excl += deg0[i] + deg1[i]; }
    if (tid == 1023) rowptr[N] = part[1023];
}

__global__ void k_fill(const int* __restrict__ ei, const float* __restrict__ attr,
                       const int* __restrict__ rowptr, int* __restrict__ cur,
                       int* __restrict__ col, int E) {
    int e = blockIdx.x * blockDim.x + threadIdx.x;
    if (e >= E) return;
    int src = ei[e];
    int dst = ei[E + e];
    float a0 = attr[2 * e], a1 = attr[2 * e + 1];
    int r = (a1 > a0) ? 1 : 0;
    int pos = rowptr[dst] + atomicAdd(&cur[dst], 1);
    col[pos] = src | (r << 30);
}

// ---------------- tf32 tensor-core GEMM ----------------
// C[M x 96cols-per-ychunk] = A[M x K] @ B[K x 96]  (B row-major [k][d])
// block: 256 thr = 8 warps (4 M-warps x 2 N-warps); tile M=128, N=96, K-chunk=32
__device__ __forceinline__ uint32_t f2tf(float f) {
    uint32_t u; asm("cvt.rna.tf32.f32 %0, %1;" : "=r"(u) : "f"(f)); return u;
}
__device__ __forceinline__ void mma_tf32(float* c, const uint32_t* a, uint32_t b0, uint32_t b1) {
    asm volatile("mma.sync.aligned.m16n8k8.row.col.f32.tf32.tf32.f32 "
        "{%0,%1,%2,%3}, {%4,%5,%6,%7}, {%8,%9}, {%0,%1,%2,%3};"
        : "+f"(c[0]), "+f"(c[1]), "+f"(c[2]), "+f"(c[3])
        : "r"(a[0]), "r"(a[1]), "r"(a[2]), "r"(a[3]), "r"(b0), "r"(b1));
}

#define AS_LD 36   // padded row stride (floats) for A smem
#define BS_LD 100  // padded row stride for B smem

__global__ __launch_bounds__(256) void k_gemm(
    const float* __restrict__ A, int M, int K,
    const float* __restrict__ B0, const float* __restrict__ B1, const float* __restrict__ B2,
    float* __restrict__ C, int ldc, const float* __restrict__ bias, int relu)
{
    __shared__ float As[128 * AS_LD];
    __shared__ float Bs[32 * BS_LD];
    const float* B = (blockIdx.y == 0) ? B0 : ((blockIdx.y == 1) ? B1 : B2);

    int tid = threadIdx.x;
    int lane = tid & 31;
    int warp = tid >> 5;
    int g = lane >> 2, tig = lane & 3;
    int mw = warp & 3;      // 0..3 -> rows mw*32
    int nw = warp >> 2;     // 0..1 -> cols nw*48
    int rowblock = blockIdx.x * 128;

    float c[2][6][4];
#pragma unroll
    for (int i = 0; i < 2; i++)
#pragma unroll
        for (int j = 0; j < 6; j++)
#pragma unroll
            for (int q = 0; q < 4; q++) c[i][j][q] = 0.f;

    const float4 z4 = make_float4(0.f, 0.f, 0.f, 0.f);
    for (int kb = 0; kb < K; kb += 32) {
        // stage A: 128 rows x 32 k (1024 float4, 4 per thread)
#pragma unroll
        for (int i = 0; i < 4; i++) {
            int id = tid + 256 * i;
            int r = id >> 3, f4 = id & 7;
            int gr = rowblock + r;
            float4 v = (gr < M) ? __ldg((const float4*)(A + (size_t)gr * K + kb) + f4) : z4;
            *(float4*)(&As[r * AS_LD + f4 * 4]) = v;
        }
        // stage B: 32 k x 96 cols (768 float4, 3 per thread)
#pragma unroll
        for (int i = 0; i < 3; i++) {
            int id = tid + 256 * i;
            int r = id / 24, f4 = id % 24;
            float4 v = __ldg((const float4*)(B + (size_t)(kb + r) * 96) + f4);
            *(float4*)(&Bs[r * BS_LD + f4 * 4]) = v;
        }
        __syncthreads();
#pragma unroll
        for (int k8 = 0; k8 < 32; k8 += 8) {
            uint32_t a[2][4];
#pragma unroll
            for (int mt = 0; mt < 2; mt++) {
                int rb = mw * 32 + mt * 16;
                a[mt][0] = f2tf(As[(rb + g) * AS_LD + k8 + tig]);
                a[mt][1] = f2tf(As[(rb + g + 8) * AS_LD + k8 + tig]);
                a[mt][2] = f2tf(As[(rb + g) * AS_LD + k8 + tig + 4]);
                a[mt][3] = f2tf(As[(rb + g + 8) * AS_LD + k8 + tig + 4]);
            }
#pragma unroll
            for (int nt = 0; nt < 6; nt++) {
                int cb = nw * 48 + nt * 8;
                uint32_t b0 = f2tf(Bs[(k8 + tig) * BS_LD + cb + g]);
                uint32_t b1 = f2tf(Bs[(k8 + tig + 4) * BS_LD + cb + g]);
                mma_tf32(c[0][nt], a[0], b0, b1);
                mma_tf32(c[1][nt], a[1], b0, b1);
            }
        }
        __syncthreads();
    }
    // store (float2 per c-pair)
    int colchunk = blockIdx.y * 96;
#pragma unroll
    for (int mt = 0; mt < 2; mt++) {
        int r0 = rowblock + mw * 32 + mt * 16 + g;
        int r1 = r0 + 8;
#pragma unroll
        for (int nt = 0; nt < 6; nt++) {
            int col = nw * 48 + nt * 8 + 2 * tig;
            float bx = 0.f, by = 0.f;
            if (bias) { bx = __ldg(bias + col); by = __ldg(bias + col + 1); }
            float v0 = c[mt][nt][0] + bx, v1 = c[mt][nt][1] + by;
            float v2 = c[mt][nt][2] + bx, v3 = c[mt][nt][3] + by;
            if (relu) {
                v0 = fmaxf(v0, 0.f); v1 = fmaxf(v1, 0.f);
                v2 = fmaxf(v2, 0.f); v3 = fmaxf(v3, 0.f);
            }
            if (r0 < M) *(float2*)(C + (size_t)r0 * ldc + colchunk + col) = make_float2(v0, v1);
            if (r1 < M) *(float2*)(C + (size_t)r1 * ldc + colchunk + col) = make_float2(v2, v3);
        }
    }
}

// ---------------- fused gather + mean + bias + relu epilogue ----------------
// out[n][d] = relu(bias[d] + T[n][d] + sum_{e:r=0} T[src][96+d]/c0 + sum_{e:r=1} T[src][192+d]/c1)
__global__ void k_aggout(const float* __restrict__ T, const int* __restrict__ rowptr,
                         const int* __restrict__ col, const int* __restrict__ deg0,
                         const int* __restrict__ deg1, const float* __restrict__ bias,
                         float* __restrict__ out, int N) {
    int warpi = (blockIdx.x * blockDim.x + threadIdx.x) >> 5;
    int lane = threadIdx.x & 31;
    if (warpi >= N) return;
    int n = warpi;
    int e0 = rowptr[n], e1 = rowptr[n + 1];
    float x0 = 0.f, x1 = 0.f, x2 = 0.f;   // relation 0
    float y0 = 0.f, y1 = 0.f, y2 = 0.f;   // relation 1
    int e = e0;
    for (; e + 1 < e1; e += 2) {
        int pa = __ldg(&col[e]);
        int pb = __ldg(&col[e + 1]);
        const float* ta = T + (size_t)(pa & 0x3FFFFFFF) * 288 + 96 + ((pa >> 30) & 1) * 96;
        const float* tb = T + (size_t)(pb & 0x3FFFFFFF) * 288 + 96 + ((pb >> 30) & 1) * 96;
        float a0v = __ldg(ta + lane), a1v = __ldg(ta + lane + 32), a2v = __ldg(ta + lane + 64);
        float b0v = __ldg(tb + lane), b1v = __ldg(tb + lane + 32), b2v = __ldg(tb + lane + 64);
        if (pa & (1 << 30)) { y0 += a0v; y1 += a1v; y2 += a2v; }
        else                { x0 += a0v; x1 += a1v; x2 += a2v; }
        if (pb & (1 << 30)) { y0 += b0v; y1 += b1v; y2 += b2v; }
        else                { x0 += b0v; x1 += b1v; x2 += b2v; }
    }
    if (e < e1) {
        int p = __ldg(&col[e]);
        const float* tr = T + (size_t)(p & 0x3FFFFFFF) * 288 + 96 + ((p >> 30) & 1) * 96;
        float v0 = __ldg(tr + lane), v1 = __ldg(tr + lane + 32), v2 = __ldg(tr + lane + 64);
        if (p & (1 << 30)) { y0 += v0; y1 += v1; y2 += v2; }
        else               { x0 += v0; x1 += v1; x2 += v2; }
    }
    float i0 = 1.f / fmaxf((float)__ldg(&deg0[n]), 1.f);
    float i1 = 1.f / fmaxf((float)__ldg(&deg1[n]), 1.f);
    const float* tr = T + (size_t)n * 288;
    float r0 = __ldg(tr + lane), r1 = __ldg(tr + lane + 32), r2 = __ldg(tr + lane + 64);
    float b0 = __ldg(bias + lane), b1 = __ldg(bias + lane + 32), b2 = __ldg(bias + lane + 64);
    float* o = out + (size_t)n * DD;
    o[lane]      = fmaxf(b0 + r0 + x0 * i0 + y0 * i1, 0.f);
    o[lane + 32] = fmaxf(b1 + r1 + x1 * i0 + y1 * i1, 0.f);
    o[lane + 64] = fmaxf(b2 + r2 + x2 * i0 + y2 * i1, 0.f);
}

// ---------------- launch ----------------
extern "C" void kernel_launch(void* const* d_in, const int* in_sizes, int n_in,
                              void* d_out, int out_size) {
    const float* x    = (const float*)d_in[0];
    const int*   ei   = (const int*)d_in[1];
    const float* attr = (const float*)d_in[2];
    const float* Wf   = (const float*)d_in[3];
    const float* bf   = (const float*)d_in[4];
    const float* W    = (const float*)d_in[5];
    const float* root = (const float*)d_in[6];
    const float* bias = (const float*)d_in[7];
    float* out = (float*)d_out;

    int E = in_sizes[1] / 2;
    int N = in_sizes[0] / FF;

    void *pA, *pB, *pT, *pWfT, *pd0, *pd1, *prp, *pc, *pcol;
    cudaGetSymbolAddress(&pA, g_hA);
    cudaGetSymbolAddress(&pB, g_hB);
    cudaGetSymbolAddress(&pT, g_T);
    cudaGetSymbolAddress(&pWfT, g_WfT);
    cudaGetSymbolAddress(&pd0, g_deg0);
    cudaGetSymbolAddress(&pd1, g_deg1);
    cudaGetSymbolAddress(&prp, g_rowptr);
    cudaGetSymbolAddress(&pc, g_cur);
    cudaGetSymbolAddress(&pcol, g_col);

    // 1: prep (zero counters + transpose Wf)
    k_prep<<<(N + 255) / 256, 256>>>(Wf, (float*)pWfT, (int*)pd0, (int*)pd1, (int*)pc, N);
    // 2-4: CSR build
    k_hist<<<(E + 255) / 256, 256>>>(ei, attr, (int*)pd0, (int*)pd1, E);
    k_scan<<<1, 1024>>>((int*)pd0, (int*)pd1, (int*)prp, N);
    k_fill<<<(E + 255) / 256, 256>>>(ei, attr, (int*)prp, (int*)pc, (int*)pcol, E);

    int mblocks = (N + 127) / 128;
    // 5: h = relu(x @ WfT + bf)   [N,128]@[128,96]
    k_gemm<<<dim3(mblocks, 1), 256>>>(x, N, FF, (const float*)pWfT, nullptr, nullptr,
                                      (float*)pA, DD, bf, 1);

    const float* W0 = W;
    const float* W1 = W + DD * DD;
    float* hin = (float*)pA;
    float* hout = (float*)pB;
    for (int it = 0; it < 3; it++) {
        // T = h @ [root | W0 | W1]   (3 y-chunks of 96 cols each)
        k_gemm<<<dim3(mblocks, 3), 256>>>(hin, N, DD, root, W0, W1,
                                          (float*)pT, 3 * DD, nullptr, 0);
        float* o = (it == 2) ? out : hout;
        k_aggout<<<(N * 32 + 255) / 256, 256>>>((const float*)pT, (int*)prp, (int*)pcol,
                                                (int*)pd0, (int*)pd1, bias, o, N);
        float* t = hin; hin = hout; hout = t;
    }
}